// round 4
// baseline (speedup 1.0000x reference)
#include <cuda_runtime.h>
#include <cstdint>
#include <math.h>

#define KK     15
#define HW     128
#define PLANE  16384
#define CIN    768
#define NSO    24
#define NF     48          // filter rows (N dim)
#define RT     8           // output rows (M-tiles) per CTA
#define RING   9
#define NCHUNK 22          // RT + 14

// ---- smem layout (bytes) for tcgen05 path ----
#define SM_TMEM   0
#define SM_MBAR   64                       // 15 mbarriers x 8B
#define SM_A      1024
#define SLOT_B    16384                    // 128 rows x 128B
#define SM_B0     (SM_A + RING*SLOT_B)     // 148480
#define SM_B1     (SM_B0 + 6144)           // 154624
#define SM_X      (SM_B1 + 6144)           // 160768
#define SM_TOTAL  (SM_X + NCHUNK*HW*4 + 128)  // 172160

// idesc: dfmt=F32(1)<<4 | afmt=TF32(2)<<7 | bfmt=TF32(2)<<10 | (N/8)<<17 | (M/16)<<24
#define IDESC_TF32 ((1u<<4) | (2u<<7) | (2u<<10) | ((NF/8)<<17) | ((128/16)<<24))

// Does this compilation pass have sm_103a arch-specific instructions?
#if defined(__CUDA_ARCH__) && (defined(__CUDA_ARCH_FEAT_SM103_ALL) || defined(__CUDA_ARCH_SPECIFIC__))
#define HAS_TCGEN05 1
#else
#define HAS_TCGEN05 0
#endif

typedef unsigned long long u64;

// Scratch (.bss)
__device__ float g_mag[(size_t)4 * CIN * PLANE];   // [b][c*24+so][y*128+x]
__device__ float g_z[(size_t)128 * PLANE];
__device__ float g_stats[256];

// ---------------- portable helpers ----------------
__device__ __forceinline__ u64 splat(float v) {
    u64 r; asm("mov.b64 %0, {%1,%1};" : "=l"(r) : "f"(v)); return r;
}
__device__ __forceinline__ void fma2(u64& d, u64 a, u64 b) {
    asm("fma.rn.f32x2 %0, %1, %2, %0;" : "+l"(d) : "l"(a), "l"(b));
}
__device__ __forceinline__ void upk2(u64 v, float& lo, float& hi) {
    asm("mov.b64 {%0,%1}, %2;" : "=f"(lo), "=f"(hi) : "l"(v));
}

#if HAS_TCGEN05
// ---------------- sm_103a-only PTX helpers ----------------
__device__ __forceinline__ uint32_t smem_u32(const void* p) {
    uint32_t a;
    asm("{ .reg .u64 t; cvta.to.shared.u64 t, %1; cvt.u32.u64 %0, t; }" : "=r"(a) : "l"(p));
    return a;
}
__device__ __forceinline__ uint32_t elect1() {
    uint32_t p;
    asm volatile("{ .reg .pred p; elect.sync _|p, 0xFFFFFFFF; selp.b32 %0,1,0,p; }" : "=r"(p));
    return p;
}
__device__ __forceinline__ float tf32r(float v) {
    uint32_t r; asm("cvt.rna.tf32.f32 %0, %1;" : "=r"(r) : "f"(v));
    return __uint_as_float(r);
}
#define SWZ(o) ((o) ^ ((((uint32_t)(o)) >> 3) & 0x70))

static __device__ __forceinline__ uint64_t mkdesc(uint32_t addr) {
    const uint64_t base = (uint64_t(2) << 61) | (uint64_t(1) << 46)
                        | (uint64_t(64) << 32) | (uint64_t(1) << 16);  // SW128, Blackwell
    return base | ((uint64_t)(addr >> 4) & 0x3FFF);
}
__device__ __forceinline__ void tmem_alloc(uint32_t smem_addr, uint32_t ncols) {
    asm volatile("tcgen05.alloc.cta_group::1.sync.aligned.shared::cta.b32 [%0], %1;"
                 :: "r"(smem_addr), "r"(ncols) : "memory");
}
__device__ __forceinline__ void tmem_relinq() {
    asm volatile("tcgen05.relinquish_alloc_permit.cta_group::1.sync.aligned;");
}
__device__ __forceinline__ void tmem_dealloc(uint32_t tmem, uint32_t ncols) {
    asm volatile("tcgen05.dealloc.cta_group::1.sync.aligned.b32 %0, %1;" :: "r"(tmem), "r"(ncols));
}
__device__ __forceinline__ void mbar_init(uint32_t a, uint32_t cnt) {
    asm volatile("mbarrier.init.shared.b64 [%0], %1;" :: "r"(a), "r"(cnt) : "memory");
}
__device__ __forceinline__ void mbar_inval(uint32_t a) {
    asm volatile("mbarrier.inval.shared.b64 [%0];" :: "r"(a) : "memory");
}
__device__ __forceinline__ void mbar_wait(uint32_t a, uint32_t par) {
    uint32_t done;
    asm volatile("{ .reg .pred p; mbarrier.try_wait.parity.acquire.cta.shared::cta.b64 p, [%1], %2;"
                 " selp.b32 %0,1,0,p; }" : "=r"(done) : "r"(a), "r"(par) : "memory");
    if (!done) {
        asm volatile("{ .reg .pred P1; WL_%=: mbarrier.try_wait.parity.acquire.cta.shared::cta.b64 P1, [%0], %1, 0x989680;"
                     " @P1 bra.uni WD_%=; bra.uni WL_%=; WD_%=: }" :: "r"(a), "r"(par) : "memory");
    }
}
__device__ __forceinline__ void mma_commit(uint32_t mbar) {
    asm volatile("tcgen05.commit.cta_group::1.mbarrier::arrive::one.shared::cluster.b64 [%0];"
                 :: "r"(mbar) : "memory");
}
__device__ __forceinline__ void mma_tf32_ss(uint32_t d, uint64_t ad, uint64_t bd, uint32_t en) {
    asm volatile("{ .reg .pred p; setp.ne.u32 p, %4, 0;"
                 " tcgen05.mma.cta_group::1.kind::tf32 [%0], %1, %2, %3, {%5,%5,%5,%5}, p; }"
                 :: "r"(d), "l"(ad), "l"(bd), "r"(IDESC_TF32), "r"(en), "r"(0u) : "memory");
}
__device__ __forceinline__ void fence_async_shared() {
    asm volatile("fence.proxy.async.shared::cta;" ::: "memory");
}
__device__ __forceinline__ void tc_fence_after() {
    asm volatile("tcgen05.fence::after_thread_sync;" ::: "memory");
}
__device__ __forceinline__ void tc_wait_ld() {
    asm volatile("tcgen05.wait::ld.sync.aligned;" ::: "memory");
}
__device__ __forceinline__ void ldtm_x32(uint32_t* r, uint32_t a) {
    asm volatile("tcgen05.ld.sync.aligned.32x32b.x32.b32 "
        "{%0,%1,%2,%3,%4,%5,%6,%7,%8,%9,%10,%11,%12,%13,%14,%15,"
        "%16,%17,%18,%19,%20,%21,%22,%23,%24,%25,%26,%27,%28,%29,%30,%31}, [%32];"
        : "=r"(r[0]),"=r"(r[1]),"=r"(r[2]),"=r"(r[3]),"=r"(r[4]),"=r"(r[5]),"=r"(r[6]),"=r"(r[7]),
          "=r"(r[8]),"=r"(r[9]),"=r"(r[10]),"=r"(r[11]),"=r"(r[12]),"=r"(r[13]),"=r"(r[14]),"=r"(r[15]),
          "=r"(r[16]),"=r"(r[17]),"=r"(r[18]),"=r"(r[19]),"=r"(r[20]),"=r"(r[21]),"=r"(r[22]),"=r"(r[23]),
          "=r"(r[24]),"=r"(r[25]),"=r"(r[26]),"=r"(r[27]),"=r"(r[28]),"=r"(r[29]),"=r"(r[30]),"=r"(r[31])
        : "r"(a));
}
__device__ __forceinline__ void ldtm_x16(uint32_t* r, uint32_t a) {
    asm volatile("tcgen05.ld.sync.aligned.32x32b.x16.b32 "
        "{%0,%1,%2,%3,%4,%5,%6,%7,%8,%9,%10,%11,%12,%13,%14,%15}, [%16];"
        : "=r"(r[0]),"=r"(r[1]),"=r"(r[2]),"=r"(r[3]),"=r"(r[4]),"=r"(r[5]),"=r"(r[6]),"=r"(r[7]),
          "=r"(r[8]),"=r"(r[9]),"=r"(r[10]),"=r"(r[11]),"=r"(r[12]),"=r"(r[13]),"=r"(r[14]),"=r"(r[15])
        : "r"(a));
}

// im2col chunk builders (3xTF32 split: cols 0-15 hi, 16-31 lo)
__device__ __forceinline__ void build_chunk(char* smem, int slot_off, int ci, int tid) {
    const float* xr = (const float*)(smem + SM_X) + ci * HW;
    for (int t = tid; t < 128 * 32; t += 256) {
        int px = t >> 5, col = t & 31, dx = col & 15;
        int sx = px + dx - 7;
        float v = (dx < 15 && sx >= 0 && sx < HW) ? xr[sx] : 0.f;
        float hi = tf32r(v);
        float val = (col >= 16) ? tf32r(v - hi) : hi;
        *(float*)(smem + slot_off + SWZ(px * 128 + col * 4)) = val;
    }
}
__device__ __forceinline__ void build_filt(char* smem, int boff, const float* __restrict__ filters,
                                           int dy, int tid) {
    for (int t = tid; t < NF * 32; t += 256) {
        int f = t >> 5, col = t & 31, dx = col & 15;
        float v = (dx < 15) ? filters[(f >> 1) * 450 + (f & 1) * 225 + dy * 15 + dx] : 0.f;
        float hi = tf32r(v);
        float val = (col >= 16) ? tf32r(v - hi) : hi;
        *(float*)(smem + boff + SWZ(f * 128 + col * 4)) = val;
    }
}
#endif  // HAS_TCGEN05

// ---------------------------------------------------------------------------
// Kernel A: Gabor conv + magnitude.
// sm_103a SASS pass: tcgen05 tf32 implicit GEMM (3xTF32).
// compute_103 PTX pass: scalar FFMA2 fallback (identical semantics & launch).
// grid (16 row-groups, 128 planes), 256 threads
// ---------------------------------------------------------------------------
__global__ __launch_bounds__(256, 1)
void gabor_mma_kernel(const float* __restrict__ x, const float* __restrict__ filters) {
#if HAS_TCGEN05
    extern __shared__ char smem[];
    const uint32_t sb = smem_u32(smem);
    const int tid = threadIdx.x, wid = tid >> 5, lid = tid & 31;
    const int plane = blockIdx.y;
    const int y0 = blockIdx.x * RT;
    const int b = plane >> 5, c = plane & 31;

    if (wid == 0) tmem_alloc(sb + SM_TMEM, 512);
    if (tid == 0)
        for (int i = 0; i < KK; ++i) mbar_init(sb + SM_MBAR + i * 8, 1);

    // stage 22 x-rows (zero-padded in y)
    const float* xp = x + (size_t)plane * PLANE;
    for (int i = tid; i < NCHUNK * HW; i += 256) {
        int rr = i >> 7, cc = i & 127;
        int gy = y0 + rr - 7;
        float v = (gy >= 0 && gy < HW) ? xp[gy * HW + cc] : 0.f;
        *(float*)(smem + SM_X + i * 4) = v;
    }
    __syncthreads();
    uint32_t tmem;
    asm volatile("ld.shared.b32 %0, [%1];" : "=r"(tmem) : "r"(sb + SM_TMEM));
    if (wid == 0) tmem_relinq();

    // prebuild chunks 0..RT-2
    for (int i = 0; i < RT - 1; ++i)
        build_chunk(smem, SM_A + (i % RING) * SLOT_B, i, tid);

    for (int dy = 0; dy < KK; ++dy) {
        if (dy >= 2) mbar_wait(sb + SM_MBAR + (dy - 2) * 8, 0);   // depth-2 pipeline
        build_chunk(smem, SM_A + ((dy + RT - 1) % RING) * SLOT_B, dy + RT - 1, tid);
        const int boff = (dy & 1) ? SM_B1 : SM_B0;
        build_filt(smem, boff, filters, dy, tid);
        fence_async_shared();
        __syncthreads();
        if (wid == 0 && elect1()) {
            uint64_t bd = mkdesc(sb + boff);
            for (int r = 0; r < RT; ++r) {
                uint64_t ad = mkdesc(sb + SM_A + ((dy + r) % RING) * SLOT_B);
                uint32_t d = tmem + r * 64;           // 64-col stride: aligned LDTM offsets
                mma_tf32_ss(d, ad + 0, bd + 0, dy > 0);  // hi x hi, k-step 0
                mma_tf32_ss(d, ad + 2, bd + 2, 1);       // hi x hi, k-step 1
                mma_tf32_ss(d, ad + 4, bd + 0, 1);       // lo x hi
                mma_tf32_ss(d, ad + 6, bd + 2, 1);
                mma_tf32_ss(d, ad + 0, bd + 4, 1);       // hi x lo
                mma_tf32_ss(d, ad + 2, bd + 6, 1);
            }
            mma_commit(sb + SM_MBAR + dy * 8);
        }
    }
    mbar_wait(sb + SM_MBAR + (KK - 1) * 8, 0);
    tc_fence_after();

    // epilogue: warps 0-3 -> tiles 0-3, warps 4-7 -> tiles 4-7
    const int sub = wid & 3;
    const int xc = sub * 32 + lid;
    const size_t mbase = ((size_t)b * CIN + (size_t)c * NSO) * PLANE + xc;
#pragma unroll
    for (int rr = 0; rr < 4; ++rr) {
        const int r = (wid >> 2) * 4 + rr;
        uint32_t rg[48];
        ldtm_x32(rg, tmem + r * 64);
        ldtm_x16(rg + 32, tmem + r * 64 + 32);
        tc_wait_ld();
        const int y = y0 + r;
#pragma unroll
        for (int s = 0; s < NSO; ++s) {
            float re = __uint_as_float(rg[2 * s]);
            float im = __uint_as_float(rg[2 * s + 1]);
            g_mag[mbase + (size_t)s * PLANE + (size_t)y * HW] = sqrtf(re * re + im * im);
        }
    }
    __syncthreads();
    if (tid == 0)
        for (int i = 0; i < KK; ++i) mbar_inval(sb + SM_MBAR + i * 8);
    __syncthreads();
    if (wid == 0) tmem_dealloc(tmem, 512);

#else  // ---------------- scalar FFMA2 fallback (compute_103 PTX pass) -------
    extern __shared__ float smf[];
    float* fs = smf;                        // [225][48]
    float* xs = smf + 225 * NF;             // [22][144] x with x-halo
    const int XW = 144;
    const int tid = threadIdx.x;
    const int plane = blockIdx.y;
    const int y0 = blockIdx.x * RT;
    const int b = plane >> 5, c = plane & 31;

    for (int i = tid; i < 225 * NF; i += 256) {
        int tap = i / NF, f = i - tap * NF;
        fs[i] = filters[(f >> 1) * 450 + (f & 1) * 225 + tap];
    }
    const float* xp = x + (size_t)plane * PLANE;
    for (int i = tid; i < NCHUNK * XW; i += 256) {
        int rr = i / XW, cc = i - rr * XW;
        int gy = y0 + rr - 7, gx = cc - 7;
        float v = (gy >= 0 && gy < HW && gx >= 0 && gx < HW) ? xp[gy * HW + gx] : 0.f;
        xs[i] = v;
    }
    __syncthreads();

    const int x0 = (tid & 31) * 4;
    const int ry = tid >> 5;
    const size_t mbase0 = ((size_t)b * CIN + (size_t)c * NSO) * PLANE
                        + (size_t)(y0 + ry) * HW + x0;
    for (int g = 0; g < 4; ++g) {
        u64 acc[4][6];
#pragma unroll
        for (int p = 0; p < 4; ++p)
#pragma unroll
            for (int s = 0; s < 6; ++s) acc[p][s] = 0ull;
        for (int dy = 0; dy < KK; ++dy) {
            const float* xr = xs + (ry + dy) * XW + x0;
            const float* wr = fs + dy * KK * NF + g * 12;
#pragma unroll
            for (int dx = 0; dx < KK; ++dx) {
                const float* w = wr + dx * NF;
                ulonglong2 wa = *(const ulonglong2*)(w);
                ulonglong2 wb = *(const ulonglong2*)(w + 4);
                ulonglong2 wc = *(const ulonglong2*)(w + 8);
                u64 wp[6] = {wa.x, wa.y, wb.x, wb.y, wc.x, wc.y};
                u64 xv[4];
#pragma unroll
                for (int p = 0; p < 4; ++p) xv[p] = splat(xr[dx + p]);
#pragma unroll
                for (int p = 0; p < 4; ++p)
#pragma unroll
                    for (int s = 0; s < 6; ++s) fma2(acc[p][s], xv[p], wp[s]);
            }
        }
#pragma unroll
        for (int s = 0; s < 6; ++s) {
            float re[4], im[4];
#pragma unroll
            for (int p = 0; p < 4; ++p) upk2(acc[p][s], re[p], im[p]);
            float4 m;
            m.x = sqrtf(re[0]*re[0] + im[0]*im[0]);
            m.y = sqrtf(re[1]*re[1] + im[1]*im[1]);
            m.z = sqrtf(re[2]*re[2] + im[2]*im[2]);
            m.w = sqrtf(re[3]*re[3] + im[3]*im[3]);
            *(float4*)(g_mag + mbase0 + (size_t)(g * 6 + s) * PLANE) = m;
        }
    }
#endif
}

// ---------------------------------------------------------------------------
// Kernel B: channel mix (FFMA2), bias dropped (cancels in instance norm)
// ---------------------------------------------------------------------------
static const int SMEM_MIX = CIN * 32 * 4;

__global__ __launch_bounds__(256, 2)
void mix_kernel(const float* __restrict__ w1) {
    extern __shared__ float w1s[];
    const int tid = threadIdx.x;
    for (int i = tid; i < CIN * 32; i += 256) {
        int j = i >> 5, o = i & 31;
        w1s[i] = w1[o * CIN + j];
    }
    __syncthreads();

    const int bb = blockIdx.y;
    const int q0 = blockIdx.x * 512 + tid * 2;
    const float* mp = g_mag + (size_t)bb * CIN * PLANE + q0;

    u64 acc[16][2];
#pragma unroll
    for (int op = 0; op < 16; ++op) { acc[op][0] = 0ull; acc[op][1] = 0ull; }

#pragma unroll 4
    for (int j = 0; j < CIN; ++j) {
        float2 m = *(const float2*)(mp + (size_t)j * PLANE);
        u64 mx = splat(m.x), my = splat(m.y);
        const ulonglong2* wrow = (const ulonglong2*)(w1s + j * 32);
#pragma unroll
        for (int q4 = 0; q4 < 8; ++q4) {
            ulonglong2 w2 = wrow[q4];
            fma2(acc[q4 * 2 + 0][0], mx, w2.x);
            fma2(acc[q4 * 2 + 0][1], my, w2.x);
            fma2(acc[q4 * 2 + 1][0], mx, w2.y);
            fma2(acc[q4 * 2 + 1][1], my, w2.y);
        }
    }
#pragma unroll
    for (int op = 0; op < 16; ++op) {
        float a0lo, a0hi, a1lo, a1hi;
        upk2(acc[op][0], a0lo, a0hi);
        upk2(acc[op][1], a1lo, a1hi);
        *(float2*)(g_z + (size_t)(bb * 32 + 2 * op)     * PLANE + q0) = make_float2(a0lo, a1lo);
        *(float2*)(g_z + (size_t)(bb * 32 + 2 * op + 1) * PLANE + q0) = make_float2(a0hi, a1hi);
    }
}

// ---------------------------------------------------------------------------
__global__ void stats_kernel() {
    const int plane = blockIdx.x;
    const float* zp = g_z + (size_t)plane * PLANE;
    const int tid = threadIdx.x;
    float s = 0.f, s2 = 0.f;
    for (int i = tid * 4; i < PLANE; i += 1024) {
        float4 v = *(const float4*)(zp + i);
        s  += v.x + v.y + v.z + v.w;
        s2 += v.x * v.x + v.y * v.y + v.z * v.z + v.w * v.w;
    }
    __shared__ float r1[256], r2[256];
    r1[tid] = s; r2[tid] = s2;
    __syncthreads();
    for (int st = 128; st > 0; st >>= 1) {
        if (tid < st) { r1[tid] += r1[tid + st]; r2[tid] += r2[tid + st]; }
        __syncthreads();
    }
    if (tid == 0) {
        float mean = r1[0] * (1.f / PLANE);
        float var  = r2[0] * (1.f / PLANE) - mean * mean;
        g_stats[plane * 2]     = mean;
        g_stats[plane * 2 + 1] = rsqrtf(var + 1e-5f);
    }
}

__global__ void norm_kernel(float* __restrict__ out) {
    __shared__ float s[32][33];
    const int plane = blockIdx.y;
    const int tile  = blockIdx.x;
    const int hb = (tile >> 2) * 32, wb = (tile & 3) * 32;
    const float mean = g_stats[plane * 2];
    const float rstd = g_stats[plane * 2 + 1];
    const float* zp = g_z + (size_t)plane * PLANE;
    float* op = out + (size_t)plane * PLANE;
    const int cc = threadIdx.x & 31;
    const int r0 = threadIdx.x >> 5;
#pragma unroll
    for (int k = 0; k < 4; ++k) {
        int rr = r0 + k * 8;
        s[rr][cc] = zp[(wb + rr) * HW + hb + cc];
    }
    __syncthreads();
#pragma unroll
    for (int k = 0; k < 4; ++k) {
        int rr = r0 + k * 8;
        op[(hb + rr) * HW + wb + cc] = (s[cc][rr] - mean) * rstd;
    }
}

// ---------------------------------------------------------------------------
extern "C" void kernel_launch(void* const* d_in, const int* in_sizes, int n_in,
                              void* d_out, int out_size) {
    const float* x       = (const float*)d_in[0];
    const float* filters = (const float*)d_in[1];
    const float* w1      = (const float*)d_in[2];
    float* out = (float*)d_out;

    cudaFuncSetAttribute(gabor_mma_kernel, cudaFuncAttributeMaxDynamicSharedMemorySize, SM_TOTAL);
    cudaFuncSetAttribute(mix_kernel,       cudaFuncAttributeMaxDynamicSharedMemorySize, SMEM_MIX);

    gabor_mma_kernel<<<dim3(16, 128), 256, SM_TOTAL>>>(x, filters);
    mix_kernel<<<dim3(32, 4), 256, SMEM_MIX>>>(w1);
    stats_kernel<<<128, 256>>>();
    norm_kernel<<<dim3(16, 128), 256>>>(out);
}

// round 5
// speedup vs baseline: 1.2692x; 1.2692x over previous
#include <cuda_runtime.h>
#include <cstdint>
#include <math.h>

#define KK     15
#define HW     128
#define PLANE  16384
#define CIN    768
#define NSO    24
#define NF     48          // filters (N dim)
#define RT     4           // output rows per CTA
#define ARING  6           // TMEM A-chunk ring slots
#define NCHUNK 18          // RT + 14 input rows per CTA

// ---- smem layout (bytes) for tcgen05 path ----
#define SM_TMEM   0
#define SM_MBAR   64                 // 15 mbarriers x 8B
#define SM_B      1024               // 4 B-slots x 6144B (48 rows x 128B, SW128)
#define SLOT_BF   6144
#define SM_X      (SM_B + 4*SLOT_BF) // 25600: 18 x-rows x 128 floats
// tcgen05 path needs 25600 + 9216 = 34816; fallback needs 53568. Launch with max.
#define SMEM_GABOR 53568

// TMEM columns: D tiles at r*64 (r=0..3, 48 used each); A ring at 256 + slot*32
#define TM_A0  256

// idesc: dfmt=F32(1)<<4 | afmt=TF32(2)<<7 | bfmt=TF32(2)<<10 | (N/8)<<17 | (M/16)<<24
#define IDESC_TF32 ((1u<<4) | (2u<<7) | (2u<<10) | ((NF/8)<<17) | ((128/16)<<24))

#if defined(__CUDA_ARCH__) && (defined(__CUDA_ARCH_FEAT_SM103_ALL) || defined(__CUDA_ARCH_SPECIFIC__))
#define HAS_TCGEN05 1
#else
#define HAS_TCGEN05 0
#endif

typedef unsigned long long u64;

// Scratch (.bss)
__device__ float g_mag[(size_t)4 * CIN * PLANE];   // [b][c*24+so][y*128+x]
__device__ float g_z[(size_t)128 * PLANE];
__device__ float g_stats[256];

// ---------------- portable helpers ----------------
__device__ __forceinline__ u64 splat(float v) {
    u64 r; asm("mov.b64 %0, {%1,%1};" : "=l"(r) : "f"(v)); return r;
}
__device__ __forceinline__ void fma2(u64& d, u64 a, u64 b) {
    asm("fma.rn.f32x2 %0, %1, %2, %0;" : "+l"(d) : "l"(a), "l"(b));
}
__device__ __forceinline__ void upk2(u64 v, float& lo, float& hi) {
    asm("mov.b64 {%0,%1}, %2;" : "=f"(lo), "=f"(hi) : "l"(v));
}

#if HAS_TCGEN05
// ---------------- sm_103a-only helpers ----------------
__device__ __forceinline__ uint32_t smem_u32(const void* p) {
    uint32_t a;
    asm("{ .reg .u64 t; cvta.to.shared.u64 t, %1; cvt.u32.u64 %0, t; }" : "=r"(a) : "l"(p));
    return a;
}
__device__ __forceinline__ uint32_t elect1() {
    uint32_t p;
    asm volatile("{ .reg .pred p; elect.sync _|p, 0xFFFFFFFF; selp.b32 %0,1,0,p; }" : "=r"(p));
    return p;
}
__device__ __forceinline__ float tf32r(float v) {
    uint32_t r; asm("cvt.rna.tf32.f32 %0, %1;" : "=r"(r) : "f"(v));
    return __uint_as_float(r);
}
#define SWZ(o) ((o) ^ ((((uint32_t)(o)) >> 3) & 0x70))

static __device__ __forceinline__ uint64_t mkdesc(uint32_t addr) {
    const uint64_t base = (uint64_t(2) << 61) | (uint64_t(1) << 46)
                        | (uint64_t(64) << 32) | (uint64_t(1) << 16);  // SW128
    return base | ((uint64_t)(addr >> 4) & 0x3FFF);
}
__device__ __forceinline__ void tmem_alloc(uint32_t smem_addr, uint32_t ncols) {
    asm volatile("tcgen05.alloc.cta_group::1.sync.aligned.shared::cta.b32 [%0], %1;"
                 :: "r"(smem_addr), "r"(ncols) : "memory");
}
__device__ __forceinline__ void tmem_relinq() {
    asm volatile("tcgen05.relinquish_alloc_permit.cta_group::1.sync.aligned;");
}
__device__ __forceinline__ void tmem_dealloc(uint32_t tmem, uint32_t ncols) {
    asm volatile("tcgen05.dealloc.cta_group::1.sync.aligned.b32 %0, %1;" :: "r"(tmem), "r"(ncols));
}
__device__ __forceinline__ void mbar_init(uint32_t a, uint32_t cnt) {
    asm volatile("mbarrier.init.shared.b64 [%0], %1;" :: "r"(a), "r"(cnt) : "memory");
}
__device__ __forceinline__ void mbar_inval(uint32_t a) {
    asm volatile("mbarrier.inval.shared.b64 [%0];" :: "r"(a) : "memory");
}
__device__ __forceinline__ void mbar_wait(uint32_t a, uint32_t par) {
    uint32_t done;
    asm volatile("{ .reg .pred p; mbarrier.try_wait.parity.acquire.cta.shared::cta.b64 p, [%1], %2;"
                 " selp.b32 %0,1,0,p; }" : "=r"(done) : "r"(a), "r"(par) : "memory");
    if (!done) {
        asm volatile("{ .reg .pred P1; WL_%=: mbarrier.try_wait.parity.acquire.cta.shared::cta.b64 P1, [%0], %1, 0x989680;"
                     " @P1 bra.uni WD_%=; bra.uni WL_%=; WD_%=: }" :: "r"(a), "r"(par) : "memory");
    }
}
__device__ __forceinline__ void mma_commit(uint32_t mbar) {
    asm volatile("tcgen05.commit.cta_group::1.mbarrier::arrive::one.shared::cluster.b64 [%0];"
                 :: "r"(mbar) : "memory");
}
// TS form: A in TMEM, B via SMEM descriptor
__device__ __forceinline__ void mma_tf32_ts(uint32_t d, uint32_t a, uint64_t bd, uint32_t en) {
    asm volatile("{ .reg .pred p; setp.ne.u32 p, %4, 0;"
                 " tcgen05.mma.cta_group::1.kind::tf32 [%0], [%1], %2, %3, {%5,%5,%5,%5}, p; }"
                 :: "r"(d), "r"(a), "l"(bd), "r"(IDESC_TF32), "r"(en), "r"(0u) : "memory");
}
__device__ __forceinline__ void fence_async_shared() {
    asm volatile("fence.proxy.async.shared::cta;" ::: "memory");
}
__device__ __forceinline__ void tc_fence_before() {
    asm volatile("tcgen05.fence::before_thread_sync;" ::: "memory");
}
__device__ __forceinline__ void tc_fence_after() {
    asm volatile("tcgen05.fence::after_thread_sync;" ::: "memory");
}
__device__ __forceinline__ void tc_wait_st() {
    asm volatile("tcgen05.wait::st.sync.aligned;" ::: "memory");
}
__device__ __forceinline__ void tc_wait_ld() {
    asm volatile("tcgen05.wait::ld.sync.aligned;" ::: "memory");
}
__device__ __forceinline__ void sttm_x32(uint32_t a, const uint32_t* r) {
    asm volatile("tcgen05.st.sync.aligned.32x32b.x32.b32 [%0], "
        "{%1,%2,%3,%4,%5,%6,%7,%8,%9,%10,%11,%12,%13,%14,%15,%16,"
        "%17,%18,%19,%20,%21,%22,%23,%24,%25,%26,%27,%28,%29,%30,%31,%32};"
        :: "r"(a),
           "r"(r[0]),"r"(r[1]),"r"(r[2]),"r"(r[3]),"r"(r[4]),"r"(r[5]),"r"(r[6]),"r"(r[7]),
           "r"(r[8]),"r"(r[9]),"r"(r[10]),"r"(r[11]),"r"(r[12]),"r"(r[13]),"r"(r[14]),"r"(r[15]),
           "r"(r[16]),"r"(r[17]),"r"(r[18]),"r"(r[19]),"r"(r[20]),"r"(r[21]),"r"(r[22]),"r"(r[23]),
           "r"(r[24]),"r"(r[25]),"r"(r[26]),"r"(r[27]),"r"(r[28]),"r"(r[29]),"r"(r[30]),"r"(r[31])
        : "memory");
}
__device__ __forceinline__ void ldtm_x32(uint32_t* r, uint32_t a) {
    asm volatile("tcgen05.ld.sync.aligned.32x32b.x32.b32 "
        "{%0,%1,%2,%3,%4,%5,%6,%7,%8,%9,%10,%11,%12,%13,%14,%15,"
        "%16,%17,%18,%19,%20,%21,%22,%23,%24,%25,%26,%27,%28,%29,%30,%31}, [%32];"
        : "=r"(r[0]),"=r"(r[1]),"=r"(r[2]),"=r"(r[3]),"=r"(r[4]),"=r"(r[5]),"=r"(r[6]),"=r"(r[7]),
          "=r"(r[8]),"=r"(r[9]),"=r"(r[10]),"=r"(r[11]),"=r"(r[12]),"=r"(r[13]),"=r"(r[14]),"=r"(r[15]),
          "=r"(r[16]),"=r"(r[17]),"=r"(r[18]),"=r"(r[19]),"=r"(r[20]),"=r"(r[21]),"=r"(r[22]),"=r"(r[23]),
          "=r"(r[24]),"=r"(r[25]),"=r"(r[26]),"=r"(r[27]),"=r"(r[28]),"=r"(r[29]),"=r"(r[30]),"=r"(r[31])
        : "r"(a));
}
__device__ __forceinline__ void ldtm_x16(uint32_t* r, uint32_t a) {
    asm volatile("tcgen05.ld.sync.aligned.32x32b.x16.b32 "
        "{%0,%1,%2,%3,%4,%5,%6,%7,%8,%9,%10,%11,%12,%13,%14,%15}, [%16];"
        : "=r"(r[0]),"=r"(r[1]),"=r"(r[2]),"=r"(r[3]),"=r"(r[4]),"=r"(r[5]),"=r"(r[6]),"=r"(r[7]),
          "=r"(r[8]),"=r"(r[9]),"=r"(r[10]),"=r"(r[11]),"=r"(r[12]),"=r"(r[13]),"=r"(r[14]),"=r"(r[15])
        : "r"(a));
}

// Build one im2col A-chunk for input row ci directly into TMEM (warps 0-3).
// TMEM layout: rows = 128 x-positions, cols 0-15 = hi(dx), 16-31 = lo(dx).
__device__ __forceinline__ void build_chunk_tmem(const float* __restrict__ xs,
                                                 uint32_t tmem_a, int ci, int wid, int lid) {
    const float* xr = xs + ci * HW;
    const int xpos = (wid << 5) + lid;
    uint32_t regs[32];
#pragma unroll
    for (int dx = 0; dx < 16; ++dx) {
        int sx = xpos + dx - 7;
        float v = (dx < 15 && sx >= 0 && sx < HW) ? xr[sx] : 0.f;
        float hi = tf32r(v);
        regs[dx]      = __float_as_uint(hi);
        regs[16 + dx] = __float_as_uint(tf32r(v - hi));
    }
    sttm_x32(tmem_a + ((uint32_t)wid << 21), regs);
}
// Filters for one dy into SMEM (SW128): cols 0-15 hi, 16-31 lo. Threads 128-255.
__device__ __forceinline__ void build_filt(char* smem, int boff, const float* __restrict__ filters,
                                           int dy, int t) {
    for (int i = t; i < NF * 32; i += 128) {
        int f = i >> 5, col = i & 31, dx = col & 15;
        float v = (dx < 15) ? filters[(f >> 1) * 450 + (f & 1) * 225 + dy * 15 + dx] : 0.f;
        float hi = tf32r(v);
        float val = (col >= 16) ? tf32r(v - hi) : hi;
        *(float*)(smem + boff + SWZ(f * 128 + col * 4)) = val;
    }
}
#endif  // HAS_TCGEN05

// ---------------------------------------------------------------------------
// Kernel A: Gabor conv + magnitude.
// sm_103a: tcgen05 tf32 TS-mode implicit GEMM (A im2col in TMEM, 3xTF32).
// grid (32 row-groups, 128 planes), 256 threads
// ---------------------------------------------------------------------------
__global__ __launch_bounds__(256, 1)
void gabor_mma_kernel(const float* __restrict__ x, const float* __restrict__ filters) {
#if HAS_TCGEN05
    extern __shared__ char smem[];
    const uint32_t sb = smem_u32(smem);
    const int tid = threadIdx.x, wid = tid >> 5, lid = tid & 31;
    const int plane = blockIdx.y;
    const int y0 = blockIdx.x * RT;
    const int b = plane >> 5, c = plane & 31;

    if (wid == 0) tmem_alloc(sb + SM_TMEM, 512);
    if (tid == 0)
        for (int i = 0; i < KK; ++i) mbar_init(sb + SM_MBAR + i * 8, 1);

    // stage NCHUNK x-rows (zero-padded in y)
    const float* xp = x + (size_t)plane * PLANE;
    float* xs = (float*)(smem + SM_X);
    for (int i = tid; i < NCHUNK * HW; i += 256) {
        int rr = i >> 7, cc = i & 127;
        int gy = y0 + rr - 7;
        xs[i] = (gy >= 0 && gy < HW) ? xp[gy * HW + cc] : 0.f;
    }
    __syncthreads();
    uint32_t tmem;
    asm volatile("ld.shared.b32 %0, [%1];" : "=r"(tmem) : "r"(sb + SM_TMEM));
    if (wid == 0) tmem_relinq();

    // prebuild A chunks 0..2 into TMEM ring slots 0..2
    if (wid < 4) {
        for (int ci = 0; ci < RT - 1; ++ci)
            build_chunk_tmem(xs, tmem + TM_A0 + ci * 32, ci, wid, lid);
        tc_wait_st();
    }

    for (int dy = 0; dy < KK; ++dy) {
        if (dy >= 3) mbar_wait(sb + SM_MBAR + (dy - 3) * 8, 0);   // depth-3 pipeline
        if (wid < 4) {
            // build A chunk dy+3 into ring slot (dy+3)%ARING
            build_chunk_tmem(xs, tmem + TM_A0 + ((dy + 3) % ARING) * 32, dy + 3, wid, lid);
            tc_wait_st();
        } else {
            build_filt(smem, SM_B + (dy & 3) * SLOT_BF, filters, dy, tid - 128);
        }
        tc_fence_before();
        fence_async_shared();
        __syncthreads();
        if (wid == 0) {
            tc_fence_after();
            if (elect1()) {
                uint64_t bd = mkdesc(sb + SM_B + (dy & 3) * SLOT_BF);
#pragma unroll
                for (int r = 0; r < RT; ++r) {
                    uint32_t a = tmem + TM_A0 + ((dy + r) % ARING) * 32;
                    uint32_t d = tmem + r * 64;
                    mma_tf32_ts(d, a + 0,  bd + 0, dy > 0);  // hi x hi, k0
                    mma_tf32_ts(d, a + 8,  bd + 2, 1);       // hi x hi, k1
                    mma_tf32_ts(d, a + 16, bd + 0, 1);       // lo x hi, k0
                    mma_tf32_ts(d, a + 24, bd + 2, 1);       // lo x hi, k1
                    mma_tf32_ts(d, a + 0,  bd + 4, 1);       // hi x lo, k0
                    mma_tf32_ts(d, a + 8,  bd + 6, 1);       // hi x lo, k1
                }
                mma_commit(sb + SM_MBAR + dy * 8);
            }
        }
    }
    mbar_wait(sb + SM_MBAR + (KK - 1) * 8, 0);
    tc_fence_after();

    // epilogue: warps 0-3 -> tiles 0,1 ; warps 4-7 -> tiles 2,3 ; sub = wid&3
    const int sub = wid & 3;
    const int xc = sub * 32 + lid;
    const size_t mbase = ((size_t)b * CIN + (size_t)c * NSO) * PLANE + xc;
#pragma unroll
    for (int rr = 0; rr < 2; ++rr) {
        const int r = (wid >> 2) * 2 + rr;
        uint32_t rg[48];
        ldtm_x32(rg, tmem + r * 64);
        ldtm_x16(rg + 32, tmem + r * 64 + 32);
        tc_wait_ld();
        const int y = y0 + r;
#pragma unroll
        for (int s = 0; s < NSO; ++s) {
            float re = __uint_as_float(rg[2 * s]);
            float im = __uint_as_float(rg[2 * s + 1]);
            g_mag[mbase + (size_t)s * PLANE + (size_t)y * HW] = sqrtf(re * re + im * im);
        }
    }
    __syncthreads();
    if (tid == 0)
        for (int i = 0; i < KK; ++i) mbar_inval(sb + SM_MBAR + i * 8);
    __syncthreads();
    if (wid == 0) tmem_dealloc(tmem, 512);

#else  // ---------------- scalar FFMA2 fallback (non-arch-specific pass) -----
    extern __shared__ float smf[];
    float* fs = smf;                        // [225][48]
    float* xs = smf + 225 * NF;             // [18][144]
    const int XW = 144;
    const int tid = threadIdx.x;
    const int plane = blockIdx.y;
    const int y0 = blockIdx.x * RT;
    const int b = plane >> 5, c = plane & 31;

    for (int i = tid; i < 225 * NF; i += 256) {
        int tap = i / NF, f = i - tap * NF;
        fs[i] = filters[(f >> 1) * 450 + (f & 1) * 225 + tap];
    }
    const float* xp = x + (size_t)plane * PLANE;
    for (int i = tid; i < NCHUNK * XW; i += 256) {
        int rr = i / XW, cc = i - rr * XW;
        int gy = y0 + rr - 7, gx = cc - 7;
        xs[i] = (gy >= 0 && gy < HW && gx >= 0 && gx < HW) ? xp[gy * HW + gx] : 0.f;
    }
    __syncthreads();

    const int x0 = (tid & 63) * 2;
    const int ry = tid >> 6;
    const size_t mbase0 = ((size_t)b * CIN + (size_t)c * NSO) * PLANE
                        + (size_t)(y0 + ry) * HW + x0;
    for (int g = 0; g < 4; ++g) {
        u64 acc[2][6];
#pragma unroll
        for (int p = 0; p < 2; ++p)
#pragma unroll
            for (int s = 0; s < 6; ++s) acc[p][s] = 0ull;
        for (int dy = 0; dy < KK; ++dy) {
            const float* xr = xs + (ry + dy) * XW + x0;
            const float* wr = fs + dy * KK * NF + g * 12;
#pragma unroll
            for (int dx = 0; dx < KK; ++dx) {
                const float* w = wr + dx * NF;
                ulonglong2 wa = *(const ulonglong2*)(w);
                ulonglong2 wb = *(const ulonglong2*)(w + 4);
                ulonglong2 wc = *(const ulonglong2*)(w + 8);
                u64 wp[6] = {wa.x, wa.y, wb.x, wb.y, wc.x, wc.y};
                u64 xv[2] = {splat(xr[dx]), splat(xr[dx + 1])};
#pragma unroll
                for (int p = 0; p < 2; ++p)
#pragma unroll
                    for (int s = 0; s < 6; ++s) fma2(acc[p][s], xv[p], wp[s]);
            }
        }
#pragma unroll
        for (int s = 0; s < 6; ++s) {
            float re0, im0, re1, im1;
            upk2(acc[0][s], re0, im0);
            upk2(acc[1][s], re1, im1);
            float2 m = make_float2(sqrtf(re0*re0 + im0*im0), sqrtf(re1*re1 + im1*im1));
            *(float2*)(g_mag + mbase0 + (size_t)(g * 6 + s) * PLANE) = m;
        }
    }
#endif
}

// ---------------------------------------------------------------------------
// Kernel B: channel mix (FFMA2), bias dropped (cancels in instance norm)
// ---------------------------------------------------------------------------
static const int SMEM_MIX = CIN * 32 * 4;

__global__ __launch_bounds__(256, 2)
void mix_kernel(const float* __restrict__ w1) {
    extern __shared__ float w1s[];
    const int tid = threadIdx.x;
    for (int i = tid; i < CIN * 32; i += 256) {
        int j = i >> 5, o = i & 31;
        w1s[i] = w1[o * CIN + j];
    }
    __syncthreads();

    const int bb = blockIdx.y;
    const int q0 = blockIdx.x * 512 + tid * 2;
    const float* mp = g_mag + (size_t)bb * CIN * PLANE + q0;

    u64 acc[16][2];
#pragma unroll
    for (int op = 0; op < 16; ++op) { acc[op][0] = 0ull; acc[op][1] = 0ull; }

#pragma unroll 4
    for (int j = 0; j < CIN; ++j) {
        float2 m = *(const float2*)(mp + (size_t)j * PLANE);
        u64 mx = splat(m.x), my = splat(m.y);
        const ulonglong2* wrow = (const ulonglong2*)(w1s + j * 32);
#pragma unroll
        for (int q4 = 0; q4 < 8; ++q4) {
            ulonglong2 w2 = wrow[q4];
            fma2(acc[q4 * 2 + 0][0], mx, w2.x);
            fma2(acc[q4 * 2 + 0][1], my, w2.x);
            fma2(acc[q4 * 2 + 1][0], mx, w2.y);
            fma2(acc[q4 * 2 + 1][1], my, w2.y);
        }
    }
#pragma unroll
    for (int op = 0; op < 16; ++op) {
        float a0lo, a0hi, a1lo, a1hi;
        upk2(acc[op][0], a0lo, a0hi);
        upk2(acc[op][1], a1lo, a1hi);
        *(float2*)(g_z + (size_t)(bb * 32 + 2 * op)     * PLANE + q0) = make_float2(a0lo, a1lo);
        *(float2*)(g_z + (size_t)(bb * 32 + 2 * op + 1) * PLANE + q0) = make_float2(a0hi, a1hi);
    }
}

// ---------------------------------------------------------------------------
__global__ void stats_kernel() {
    const int plane = blockIdx.x;
    const float* zp = g_z + (size_t)plane * PLANE;
    const int tid = threadIdx.x;
    float s = 0.f, s2 = 0.f;
    for (int i = tid * 4; i < PLANE; i += 1024) {
        float4 v = *(const float4*)(zp + i);
        s  += v.x + v.y + v.z + v.w;
        s2 += v.x * v.x + v.y * v.y + v.z * v.z + v.w * v.w;
    }
    __shared__ float r1[256], r2[256];
    r1[tid] = s; r2[tid] = s2;
    __syncthreads();
    for (int st = 128; st > 0; st >>= 1) {
        if (tid < st) { r1[tid] += r1[tid + st]; r2[tid] += r2[tid + st]; }
        __syncthreads();
    }
    if (tid == 0) {
        float mean = r1[0] * (1.f / PLANE);
        float var  = r2[0] * (1.f / PLANE) - mean * mean;
        g_stats[plane * 2]     = mean;
        g_stats[plane * 2 + 1] = rsqrtf(var + 1e-5f);
    }
}

__global__ void norm_kernel(float* __restrict__ out) {
    __shared__ float s[32][33];
    const int plane = blockIdx.y;
    const int tile  = blockIdx.x;
    const int hb = (tile >> 2) * 32, wb = (tile & 3) * 32;
    const float mean = g_stats[plane * 2];
    const float rstd = g_stats[plane * 2 + 1];
    const float* zp = g_z + (size_t)plane * PLANE;
    float* op = out + (size_t)plane * PLANE;
    const int cc = threadIdx.x & 31;
    const int r0 = threadIdx.x >> 5;
#pragma unroll
    for (int k = 0; k < 4; ++k) {
        int rr = r0 + k * 8;
        s[rr][cc] = zp[(wb + rr) * HW + hb + cc];
    }
    __syncthreads();
#pragma unroll
    for (int k = 0; k < 4; ++k) {
        int rr = r0 + k * 8;
        op[(hb + rr) * HW + wb + cc] = (s[cc][rr] - mean) * rstd;
    }
}

// ---------------------------------------------------------------------------
extern "C" void kernel_launch(void* const* d_in, const int* in_sizes, int n_in,
                              void* d_out, int out_size) {
    const float* x       = (const float*)d_in[0];
    const float* filters = (const float*)d_in[1];
    const float* w1      = (const float*)d_in[2];
    float* out = (float*)d_out;

    cudaFuncSetAttribute(gabor_mma_kernel, cudaFuncAttributeMaxDynamicSharedMemorySize, SMEM_GABOR);
    cudaFuncSetAttribute(mix_kernel,       cudaFuncAttributeMaxDynamicSharedMemorySize, SMEM_MIX);

    gabor_mma_kernel<<<dim3(32, 128), 256, SMEM_GABOR>>>(x, filters);
    mix_kernel<<<dim3(32, 4), 256, SMEM_MIX>>>(w1);
    stats_kernel<<<128, 256>>>();
    norm_kernel<<<dim3(16, 128), 256>>>(out);
}